// round 1
// baseline (speedup 1.0000x reference)
#include <cuda_runtime.h>
#include <cuda_bf16.h>
#include <math.h>

// Problem dims
#define B_  64
#define L_  196
#define D_  2048
#define I_  512
#define M_  (B_ * L_)   // 12544

// Scratch (allocation-free: __device__ globals)
__device__ float g_hs[B_ * I_];        // hs_shaped + b_h + b_f  [B, I]
__device__ float g_t [(size_t)M_ * I_]; // fv@W_f + bias          [B*L, I]

// ---------------------------------------------------------------------------
// Kernel A: g_hs[b,i] = b_f[i] + b_h[i] + sum_k hidden[b,k] * W_h[k,i]
// grid (B, I/128), block 128
// ---------------------------------------------------------------------------
__global__ __launch_bounds__(128)
void hs_kernel(const float* __restrict__ hidden,
               const float* __restrict__ W_h,
               const float* __restrict__ b_h,
               const float* __restrict__ b_f,
               float* __restrict__ out)
{
    __shared__ float h[I_];
    const int b = blockIdx.x;
    for (int k = threadIdx.x; k < I_; k += 128)
        h[k] = hidden[b * I_ + k];
    __syncthreads();

    const int i = blockIdx.y * 128 + threadIdx.x;
    float acc = b_h[i] + b_f[i];
    #pragma unroll 8
    for (int k = 0; k < I_; k++)
        acc = fmaf(h[k], W_h[(size_t)k * I_ + i], acc);
    out[b * I_ + i] = acc;
}

// ---------------------------------------------------------------------------
// SGEMM: C[M,N] = A[M,K] @ Bm[K,N] (+ bias[N]) (+ rowBias[m/rowsPerBatch, N])
// BM=128, BN=128, BK=8, TM=8, TN=8, 256 threads. All dims divide evenly here.
// ---------------------------------------------------------------------------
#define BM 128
#define BN 128
#define BK 8
#define TM 8
#define TN 8

__global__ __launch_bounds__(256)
void sgemm_bias(int M, int N, int K,
                const float* __restrict__ A,
                const float* __restrict__ Bm,
                float* __restrict__ C,
                const float* __restrict__ bias,     // [N] or nullptr
                const float* __restrict__ rowBias,  // [?, N] or nullptr
                int rowsPerBatch)
{
    __shared__ float As[BK][BM];
    __shared__ float Bs[BK][BN];

    const int ccol = blockIdx.x;   // N-tile
    const int crow = blockIdx.y;   // M-tile

    const int tid = threadIdx.x;
    const int threadRow = tid / (BN / TN);   // 0..15
    const int threadCol = tid % (BN / TN);   // 0..15

    const float* Ab = A  + (size_t)crow * BM * K;
    const float* Bb = Bm + (size_t)ccol * BN;
    float*       Cb = C  + (size_t)crow * BM * N + (size_t)ccol * BN;

    // A tile: 128 rows x 8 cols -> 256 float4 loads (2 per row)
    const int aRow = tid >> 1;           // 0..127
    const int aCol = (tid & 1) * 4;      // 0 or 4
    // B tile: 8 rows x 128 cols -> 256 float4 loads (32 per row)
    const int bRow = tid >> 5;           // 0..7
    const int bCol = (tid & 31) * 4;

    float acc[TM][TN];
    #pragma unroll
    for (int i = 0; i < TM; i++)
        #pragma unroll
        for (int j = 0; j < TN; j++) acc[i][j] = 0.0f;

    float regM[TM], regN[TN];

    for (int k0 = 0; k0 < K; k0 += BK) {
        const float4 a4 = *(const float4*)(Ab + (size_t)aRow * K + k0 + aCol);
        As[aCol + 0][aRow] = a4.x;
        As[aCol + 1][aRow] = a4.y;
        As[aCol + 2][aRow] = a4.z;
        As[aCol + 3][aRow] = a4.w;
        const float4 b4 = *(const float4*)(Bb + (size_t)(k0 + bRow) * N + bCol);
        *(float4*)&Bs[bRow][bCol] = b4;
        __syncthreads();

        #pragma unroll
        for (int k = 0; k < BK; k++) {
            #pragma unroll
            for (int i = 0; i < TM; i++) regM[i] = As[k][threadRow * TM + i];
            #pragma unroll
            for (int j = 0; j < TN; j++) regN[j] = Bs[k][threadCol * TN + j];
            #pragma unroll
            for (int i = 0; i < TM; i++)
                #pragma unroll
                for (int j = 0; j < TN; j++)
                    acc[i][j] = fmaf(regM[i], regN[j], acc[i][j]);
        }
        __syncthreads();
    }

    #pragma unroll
    for (int i = 0; i < TM; i++) {
        const int localRow = threadRow * TM + i;
        const size_t gm = (size_t)crow * BM + localRow;
        #pragma unroll
        for (int j = 0; j < TN; j += 4) {
            const int localCol = threadCol * TN + j;
            float4 v = make_float4(acc[i][j], acc[i][j+1], acc[i][j+2], acc[i][j+3]);
            if (bias) {
                const float4 bb = *(const float4*)(bias + (size_t)ccol * BN + localCol);
                v.x += bb.x; v.y += bb.y; v.z += bb.z; v.w += bb.w;
            }
            if (rowBias) {
                const float4 rb = *(const float4*)(rowBias
                                  + (gm / rowsPerBatch) * (size_t)N
                                  + (size_t)ccol * BN + localCol);
                v.x += rb.x; v.y += rb.y; v.z += rb.z; v.w += rb.w;
            }
            *(float4*)(Cb + (size_t)localRow * N + localCol) = v;
        }
    }
}

// ---------------------------------------------------------------------------
// Kernel D: per-(b,d) softmax over L and weighted sum.
// e lives in the alpha region of d_out; alpha overwrites it in place.
// grid 512 x block 256 -> one thread per (b,d) column.
// ---------------------------------------------------------------------------
__global__ __launch_bounds__(256)
void softmax_z_kernel(float* __restrict__ e_alpha,      // [B, L, D] in/out
                      const float* __restrict__ fv,     // [B, L, D]
                      float* __restrict__ z)            // [B, D]
{
    const int idx = blockIdx.x * blockDim.x + threadIdx.x;  // 0 .. B*D-1
    const int b = idx / D_;
    const int d = idx - b * D_;

    float* ecol = e_alpha + (size_t)b * L_ * D_ + d;
    const float* fcol = fv + (size_t)b * L_ * D_ + d;

    // pass 1: online max + sum
    float m = -INFINITY, s = 0.0f;
    #pragma unroll 4
    for (int l = 0; l < L_; l++) {
        const float v = ecol[(size_t)l * D_];
        const float nm = fmaxf(m, v);
        s = s * __expf(m - nm) + __expf(v - nm);
        m = nm;
    }
    const float inv = 1.0f / s;

    // pass 2: write alpha, accumulate z
    float zz = 0.0f;
    #pragma unroll 4
    for (int l = 0; l < L_; l++) {
        const float a = __expf(ecol[(size_t)l * D_] - m) * inv;
        ecol[(size_t)l * D_] = a;
        zz = fmaf(a, fcol[(size_t)l * D_], zz);
    }
    z[idx] = zz;
}

// ---------------------------------------------------------------------------
// kernel_launch
// Inputs (metadata order): fv[B,L,D], hidden[B,I], W_f[D,I], b_f[I],
//                          W_h[I,I], b_h[I], W_a[I,D], b_a[D]
// Output: z[B,D] followed by alpha[B,L,D]
// ---------------------------------------------------------------------------
extern "C" void kernel_launch(void* const* d_in, const int* in_sizes, int n_in,
                              void* d_out, int out_size)
{
    const float* fv     = (const float*)d_in[0];
    const float* hidden = (const float*)d_in[1];
    const float* W_f    = (const float*)d_in[2];
    const float* b_f    = (const float*)d_in[3];
    const float* W_h    = (const float*)d_in[4];
    const float* b_h    = (const float*)d_in[5];
    const float* W_a    = (const float*)d_in[6];
    const float* b_a    = (const float*)d_in[7];

    float* z     = (float*)d_out;               // [B, D]
    float* alpha = z + (size_t)B_ * D_;         // [B, L, D] (also e scratch)

    float* hsPtr = nullptr;
    float* tPtr  = nullptr;
    cudaGetSymbolAddress((void**)&hsPtr, g_hs);
    cudaGetSymbolAddress((void**)&tPtr,  g_t);

    // 1) hs = hidden @ W_h + b_h + b_f
    hs_kernel<<<dim3(B_, I_ / 128), 128>>>(hidden, W_h, b_h, b_f, hsPtr);

    // 2) t = fv @ W_f + hs[b]        M=12544, N=512, K=2048
    sgemm_bias<<<dim3(I_ / BN, M_ / BM), 256>>>(
        M_, I_, D_, fv, W_f, tPtr, nullptr, hsPtr, L_);

    // 3) e = t @ W_a + b_a           M=12544, N=2048, K=512   (into alpha region)
    sgemm_bias<<<dim3(D_ / BN, M_ / BM), 256>>>(
        M_, D_, I_, tPtr, W_a, alpha, b_a, nullptr, 1);

    // 4) softmax over L + z
    softmax_z_kernel<<<(B_ * D_) / 256, 256>>>(alpha, fv, z);
}

// round 4
// speedup vs baseline: 3.0985x; 3.0985x over previous
#include <cuda_runtime.h>
#include <cuda_bf16.h>
#include <cstdint>
#include <math.h>

// Problem dims
#define B_  64
#define L_  196
#define D_  2048
#define I_  512
#define M_  (B_ * L_)   // 12544

// Scratch (allocation-free: __device__ globals)
__device__ float g_hs [B_ * I_];          // hs_shaped + b_h + b_f   [B, I]
__device__ float g_t  [(size_t)M_ * I_];  // fv@W_f + bias (tf32)    [B*L, I]
__device__ float g_Wft[(size_t)I_ * D_];  // W_f^T (tf32)            [I, D]
__device__ float g_Wat[(size_t)D_ * I_];  // W_a^T (tf32)            [D, I]

// ---------------------------------------------------------------------------
// helpers
// ---------------------------------------------------------------------------
__device__ __forceinline__ uint32_t smem_u32(const void* p) {
    uint32_t a;
    asm("{ .reg .u64 t; cvta.to.shared.u64 t, %1; cvt.u32.u64 %0, t; }"
        : "=r"(a) : "l"(p));
    return a;
}

// round-to-nearest (ties away) to tf32: keep top 19 bits of fp32
__device__ __forceinline__ float to_tf32(float v) {
    uint32_t u = __float_as_uint(v);
    u = (u + 0x1000u) & 0xFFFFE000u;
    return __uint_as_float(u);
}

#define MMA_TF32(c, a, b) \
    asm volatile("mma.sync.aligned.m16n8k8.row.col.f32.tf32.tf32.f32 " \
        "{%0,%1,%2,%3}, {%4,%5,%6,%7}, {%8,%9}, {%0,%1,%2,%3};" \
        : "+f"((c)[0]), "+f"((c)[1]), "+f"((c)[2]), "+f"((c)[3]) \
        : "r"((a)[0]), "r"((a)[1]), "r"((a)[2]), "r"((a)[3]), \
          "r"((b)[0]), "r"((b)[1]))

#define CP_ASYNC16(saddr, gptr) \
    asm volatile("cp.async.cg.shared.global [%0], [%1], 16;" \
                 :: "r"(saddr), "l"(gptr) : "memory")

// ---------------------------------------------------------------------------
// Kernel A: g_hs[b,i] = b_f[i] + b_h[i] + sum_k hidden[b,k] * W_h[k,i]
// ---------------------------------------------------------------------------
__global__ __launch_bounds__(128)
void hs_kernel(const float* __restrict__ hidden,
               const float* __restrict__ W_h,
               const float* __restrict__ b_h,
               const float* __restrict__ b_f,
               float* __restrict__ out)
{
    __shared__ float h[I_];
    const int b = blockIdx.x;
    for (int k = threadIdx.x; k < I_; k += 128)
        h[k] = hidden[b * I_ + k];
    __syncthreads();

    const int i = blockIdx.y * 128 + threadIdx.x;
    float acc = b_h[i] + b_f[i];
    #pragma unroll 8
    for (int k = 0; k < I_; k++)
        acc = fmaf(h[k], W_h[(size_t)k * I_ + i], acc);
    out[b * I_ + i] = acc;
}

// ---------------------------------------------------------------------------
// Transpose + tf32 round: in[R][C] -> out[C][R]
// ---------------------------------------------------------------------------
__global__ __launch_bounds__(256)
void transpose_k(const float* __restrict__ in, float* __restrict__ out,
                 int R, int Cc)
{
    __shared__ float t[32][33];
    const int bx = blockIdx.x * 32;
    const int by = blockIdx.y * 32;
    const int x = threadIdx.x, y = threadIdx.y;
    #pragma unroll
    for (int i = 0; i < 32; i += 8)
        t[y + i][x] = in[(size_t)(by + y + i) * Cc + bx + x];
    __syncthreads();
    #pragma unroll
    for (int i = 0; i < 32; i += 8)
        out[(size_t)(bx + y + i) * R + by + x] = to_tf32(t[x][y + i]);
}

// ---------------------------------------------------------------------------
// tf32 mma.sync GEMM: C[M,N] = A[M,K] @ Bt[N,K]^T (+bias[N]) (+rowBias)
// CTA 128x128x32, 4 cp.async stages, 256 threads (8 warps, warp tile 64x32).
// All dims divide evenly. cvtOut: round C to tf32 on store.
// ---------------------------------------------------------------------------
#define NSTAGE 4
#define STAGE_BYTES 32768           // A 16KB + B 16KB
#define SMEM_BYTES (NSTAGE * STAGE_BYTES)

__global__ __launch_bounds__(256)
void gemm_tc(int M, int N, int K,
             const float* __restrict__ A,
             const float* __restrict__ Bt,
             float* __restrict__ C,
             const float* __restrict__ bias,
             const float* __restrict__ rowBias,
             int rowsPerBatch, int cvtOut)
{
    extern __shared__ __align__(128) char smem[];
    const uint32_t sbase = smem_u32(smem);
    const int tid = threadIdx.x;
    const int wid = tid >> 5;
    const int lid = tid & 31;
    const int g   = lid >> 2;      // 0..7
    const int t4  = lid & 3;       // 0..3

    const int wm = wid >> 2;       // 0..1 -> 64-row slab
    const int wn = wid & 3;        // 0..3 -> 32-col slab
    const int m0 = wm * 64;
    const int n0 = wn * 32;

    const int crow = blockIdx.y, ccol = blockIdx.x;
    const float* Ab = A  + (size_t)crow * 128 * K;
    const float* Bb = Bt + (size_t)ccol * 128 * K;

    // gmem->smem mapping: j = tid + it*256; row=j>>3, chunk c4=j&7 (16B)
    const int ldRow = tid >> 1;              // not used; per-it below
    (void)ldRow;

    float cfr[4][4][4];
    #pragma unroll
    for (int mt = 0; mt < 4; mt++)
        #pragma unroll
        for (int nt = 0; nt < 4; nt++)
            #pragma unroll
            for (int q = 0; q < 4; q++) cfr[mt][nt][q] = 0.0f;

    const int nk = K >> 5;

    // stage loader: 4 x 16B per tensor per thread
    auto load_stage = [&](int ch, int s) {
        const int kc = ch * 32;
        const uint32_t sA = sbase + s * STAGE_BYTES;
        const uint32_t sB = sA + 16384;
        #pragma unroll
        for (int it = 0; it < 4; it++) {
            const int j = tid + it * 256;
            const int row = j >> 3, c4 = j & 7;
            const uint32_t swz = row * 128 + ((c4 << 4) ^ ((row & 7) << 4));
            CP_ASYNC16(sA + swz, Ab + (size_t)row * K + kc + c4 * 4);
            CP_ASYNC16(sB + swz, Bb + (size_t)row * K + kc + c4 * 4);
        }
    };

    load_stage(0, 0);
    asm volatile("cp.async.commit_group;" ::: "memory");
    load_stage(1, 1);
    asm volatile("cp.async.commit_group;" ::: "memory");

    uint32_t af[2][16], bf[2][8];

    for (int ch = 0; ch < nk; ch++) {
        const int s = ch & (NSTAGE - 1);
        if (ch + 2 < nk) load_stage(ch + 2, (ch + 2) & (NSTAGE - 1));
        asm volatile("cp.async.commit_group;" ::: "memory");
        asm volatile("cp.async.wait_group 2;" ::: "memory");
        __syncthreads();

        const char* sA = smem + s * STAGE_BYTES;
        const char* sB = sA + 16384;

        // fragment loader for k-step ks into buffer slot p
        auto load_frags = [&](int ks, int p) {
            const uint32_t col0 = (ks * 8 + t4) * 4;   // bytes
            #pragma unroll
            for (int mt = 0; mt < 4; mt++) {
                const int row = m0 + mt * 16 + g;
                const uint32_t xm = (row & 7) << 4;
                const uint32_t ro = row * 128;
                af[p][mt*4+0] = *(const uint32_t*)(sA + (ro        + (col0 ^ xm)));
                af[p][mt*4+1] = *(const uint32_t*)(sA + (ro + 1024 + (col0 ^ xm)));
                af[p][mt*4+2] = *(const uint32_t*)(sA + (ro        + ((col0+16) ^ xm)));
                af[p][mt*4+3] = *(const uint32_t*)(sA + (ro + 1024 + ((col0+16) ^ xm)));
            }
            #pragma unroll
            for (int nt = 0; nt < 4; nt++) {
                const int row = n0 + nt * 8 + g;
                const uint32_t xm = (row & 7) << 4;
                const uint32_t ro = row * 128;
                bf[p][nt*2+0] = *(const uint32_t*)(sB + (ro + (col0 ^ xm)));
                bf[p][nt*2+1] = *(const uint32_t*)(sB + (ro + ((col0+16) ^ xm)));
            }
        };

        load_frags(0, 0);
        #pragma unroll
        for (int ks = 0; ks < 4; ks++) {
            const int p = ks & 1;
            if (ks < 3) load_frags(ks + 1, p ^ 1);
            #pragma unroll
            for (int mt = 0; mt < 4; mt++)
                #pragma unroll
                for (int nt = 0; nt < 4; nt++)
                    MMA_TF32(cfr[mt][nt], &af[p][mt*4], &bf[p][nt*2]);
        }
        __syncthreads();
    }

    // Epilogue: thread owns rows (m0+mt*16+g, +8), cols n0+nt*8+t4*2 (+1)
    #pragma unroll
    for (int mt = 0; mt < 4; mt++) {
        #pragma unroll
        for (int half = 0; half < 2; half++) {
            const int ml = m0 + mt * 16 + g + half * 8;
            const size_t gm = (size_t)crow * 128 + ml;
            const float* rp = rowBias
                ? rowBias + (gm / rowsPerBatch) * (size_t)N + (size_t)ccol * 128
                : nullptr;
            float* Crow = C + gm * N + (size_t)ccol * 128;
            #pragma unroll
            for (int nt = 0; nt < 4; nt++) {
                const int cl = n0 + nt * 8 + t4 * 2;
                float v0 = cfr[mt][nt][half * 2 + 0];
                float v1 = cfr[mt][nt][half * 2 + 1];
                if (bias) { v0 += bias[(size_t)ccol * 128 + cl];
                            v1 += bias[(size_t)ccol * 128 + cl + 1]; }
                if (rp)   { v0 += rp[cl]; v1 += rp[cl + 1]; }
                if (cvtOut) { v0 = to_tf32(v0); v1 = to_tf32(v1); }
                *(float2*)(Crow + cl) = make_float2(v0, v1);
            }
        }
    }
}

// ---------------------------------------------------------------------------
// Softmax over L + z, one thread per (b,d) column. In-place on alpha region.
// ---------------------------------------------------------------------------
__global__ __launch_bounds__(256)
void softmax_z_kernel(float* __restrict__ e_alpha,
                      const float* __restrict__ fv,
                      float* __restrict__ z)
{
    const int idx = blockIdx.x * blockDim.x + threadIdx.x;
    const int b = idx / D_;
    const int d = idx - b * D_;

    float* ecol = e_alpha + (size_t)b * L_ * D_ + d;
    const float* fcol = fv + (size_t)b * L_ * D_ + d;

    float m = -INFINITY, s = 0.0f;
    #pragma unroll 4
    for (int l = 0; l < L_; l++) {
        const float v = ecol[(size_t)l * D_];
        const float nm = fmaxf(m, v);
        s = s * __expf(m - nm) + __expf(v - nm);
        m = nm;
    }
    const float inv = 1.0f / s;

    float zz = 0.0f;
    #pragma unroll 4
    for (int l = 0; l < L_; l++) {
        const float a = __expf(ecol[(size_t)l * D_] - m) * inv;
        ecol[(size_t)l * D_] = a;
        zz = fmaf(a, fcol[(size_t)l * D_], zz);
    }
    z[idx] = zz;
}

// ---------------------------------------------------------------------------
// kernel_launch
// ---------------------------------------------------------------------------
extern "C" void kernel_launch(void* const* d_in, const int* in_sizes, int n_in,
                              void* d_out, int out_size)
{
    const float* fv     = (const float*)d_in[0];
    const float* hidden = (const float*)d_in[1];
    const float* W_f    = (const float*)d_in[2];
    const float* b_f    = (const float*)d_in[3];
    const float* W_h    = (const float*)d_in[4];
    const float* b_h    = (const float*)d_in[5];
    const float* W_a    = (const float*)d_in[6];
    const float* b_a    = (const float*)d_in[7];

    float* z     = (float*)d_out;
    float* alpha = z + (size_t)B_ * D_;

    float *hsPtr, *tPtr, *WftPtr, *WatPtr;
    cudaGetSymbolAddress((void**)&hsPtr,  g_hs);
    cudaGetSymbolAddress((void**)&tPtr,   g_t);
    cudaGetSymbolAddress((void**)&WftPtr, g_Wft);
    cudaGetSymbolAddress((void**)&WatPtr, g_Wat);

    cudaFuncSetAttribute(gemm_tc, cudaFuncAttributeMaxDynamicSharedMemorySize,
                         SMEM_BYTES);

    // 0) transpose weights to K-major + tf32 round
    transpose_k<<<dim3(I_ / 32, D_ / 32), dim3(32, 8)>>>(W_f, WftPtr, D_, I_);
    transpose_k<<<dim3(D_ / 32, I_ / 32), dim3(32, 8)>>>(W_a, WatPtr, I_, D_);

    // 1) hs = hidden @ W_h + b_h + b_f
    hs_kernel<<<dim3(B_, I_ / 128), 128>>>(hidden, W_h, b_h, b_f, hsPtr);

    // 2) t = fv @ W_f + hs[b]   M=12544, N=512, K=2048  (store tf32-rounded)
    gemm_tc<<<dim3(I_ / 128, M_ / 128), 256, SMEM_BYTES>>>(
        M_, I_, D_, fv, WftPtr, tPtr, nullptr, hsPtr, L_, 1);

    // 3) e = t @ W_a + b_a      M=12544, N=2048, K=512  (into alpha region)
    gemm_tc<<<dim3(D_ / 128, M_ / 128), 256, SMEM_BYTES>>>(
        M_, D_, I_, tPtr, WatPtr, alpha, b_a, nullptr, 1, 0);

    // 4) softmax over L + z
    softmax_z_kernel<<<(B_ * D_) / 256, 256>>>(alpha, fv, z);
}